// round 13
// baseline (speedup 1.0000x reference)
#include <cuda_runtime.h>

#define S_TILE   16
#define KF       32
#define ROWS     48            // S_TILE + KF (ring buffer size)
#define CHAIN    4             // s-tiles per CTA
#define DCONST   1024
#define D4       256           // D / 4
#define PITCH4   257           // float4 pitch per row
#define COLS     48
#define RPITCH   49            // red row pitch (floats) -> conflict-free partial stores
#define WPITCH   50            // weight-row pitch in u64 (even -> 16B aligned)
#define NEG_BIG  -1.0e9f

// weight row r at WROW(r) u64; +2 stagger per 8 rows keeps h0/h1 pairs bank-clean
#define WROW(r)  ((r) * WPITCH + (((r) >> 3) << 1))
#define W_U64    800

#define TILE_F4      (ROWS * PITCH4)              // 12336 f4
#define RED_OFF      (TILE_F4 * 4)                // 49344 floats
#define RED_SIZE     (8 * S_TILE * RPITCH)        // 6272 floats
#define W_OFF        (RED_OFF + RED_SIZE)         // 55616 (byte 222464: 16B aligned)
#define SMEM_FLOATS  (W_OFF + W_U64 * 2)
#define SMEM_BYTES   (SMEM_FLOATS * 4)            // 228864 B

typedef unsigned long long u64;

__device__ __forceinline__ void fma2(u64& d, u64 a, u64 b) {
    asm("fma.rn.f32x2 %0, %1, %2, %0;" : "+l"(d) : "l"(a), "l"(b));
}
__device__ __forceinline__ float sum2(u64 a) {
    float2 v = *reinterpret_cast<float2*>(&a);
    return v.x + v.y;
}

__global__ __launch_bounds__(512, 1)
void future_encoder_kernel(const float* __restrict__ in,
                           float* __restrict__ out,
                           int S)
{
    extern __shared__ float smem[];
    ulonglong2* tileU = reinterpret_cast<ulonglong2*>(smem);
    float4*     tile4 = reinterpret_cast<float4*>(smem);
    float*      red   = smem + RED_OFF;
    u64*        Wd    = reinterpret_cast<u64*>(smem + W_OFF);
    float2*     Wd2   = reinterpret_cast<float2*>(smem + W_OFF);

    const int tid   = threadIdx.x;
    const int chain = blockIdx.x;
    const int bb    = blockIdx.y;
    const int t0    = chain * CHAIN;

    const float4* in4  = reinterpret_cast<const float4*>(in)  + (size_t)bb * S * D4;
    float4*       out4 = reinterpret_cast<float4*>(out)       + (size_t)bb * S * D4;

    // ---- initial load: 48 rows into slots 0..47 ----
    {
        const int half = tid >> 8;
        const int col  = tid & 255;
        #pragma unroll 4
        for (int it = 0; it < 24; ++it) {
            const int r = it * 2 + half;
            int gr = t0 * S_TILE + r;
            if (gr > S - 1) gr = S - 1;
            tile4[r * PITCH4 + col] = in4[(size_t)gr * D4 + col];
        }
    }

    int rot = 0;

    for (int tt = 0; tt < CHAIN; ++tt) {
        const int s0 = (t0 + tt) * S_TILE;
        __syncthreads();   // ring consistent (incl. completed cp.async refresh)

        // ===== Phase A: warp = (d-group g, j-half) =====
        {
            const int w    = tid >> 5;
            const int lane = tid & 31;
            const int g    = w >> 1;          // d-group 0..7 (128 dims)
            const int j0   = (w & 1) * 24;    // j half
            const int a    = lane >> 3;       // q rows a, a+4, a+8, a+12
            const int b    = lane & 7;        // f cols j0+b, +8, +16

            int qs[4], fs[3];
            #pragma unroll
            for (int ii = 0; ii < 4; ++ii) {
                int r = a + 4 * ii + rot; if (r >= ROWS) r -= ROWS;
                qs[ii] = r * PITCH4;
            }
            #pragma unroll
            for (int jj = 0; jj < 3; ++jj) {
                int r = j0 + b + 8 * jj + rot; if (r >= ROWS) r -= ROWS;
                fs[jj] = r * PITCH4;
            }

            u64 acc[4][3];
            #pragma unroll
            for (int ii = 0; ii < 4; ++ii)
                #pragma unroll
                for (int jj = 0; jj < 3; ++jj)
                    acc[ii][jj] = 0ull;

            const int base = g * 32;
            #pragma unroll 4
            for (int step = 0; step < 32; ++step) {
                const int col = base + step;
                ulonglong2 q[4], f[3];
                #pragma unroll
                for (int ii = 0; ii < 4; ++ii)
                    q[ii] = tileU[qs[ii] + col];
                #pragma unroll
                for (int jj = 0; jj < 3; ++jj)
                    f[jj] = tileU[fs[jj] + col];
                #pragma unroll
                for (int ii = 0; ii < 4; ++ii)
                    #pragma unroll
                    for (int jj = 0; jj < 3; ++jj) {
                        fma2(acc[ii][jj], q[ii].x, f[jj].x);
                        fma2(acc[ii][jj], q[ii].y, f[jj].y);
                    }
            }

            float* myred = red + g * (S_TILE * RPITCH);
            #pragma unroll
            for (int ii = 0; ii < 4; ++ii)
                #pragma unroll
                for (int jj = 0; jj < 3; ++jj)
                    myred[(a + 4 * ii) * RPITCH + (j0 + b + 8 * jj)] = sum2(acc[ii][jj]);
        }
        __syncthreads();   // red complete

        // ---- reduce over d-groups + mask + softmax (warp = query row) ----
        {
            const int row  = tid >> 5;
            const int lane = tid & 31;

            float s1 = 0.0f, s2 = 0.0f;
            #pragma unroll
            for (int g = 0; g < 8; ++g)
                s1 += red[g * (S_TILE * RPITCH) + row * RPITCH + lane];
            if (lane < 16) {
                #pragma unroll
                for (int g = 0; g < 8; ++g)
                    s2 += red[g * (S_TILE * RPITCH) + row * RPITCH + 32 + lane];
            }

            const int j1 = lane;
            const int k1 = j1 - row - 1;
            const bool val1 = (k1 >= 0) && (k1 < KF) && (s0 + j1 < S);
            const float v1 = val1 ? s1 : NEG_BIG;

            const int j2 = 32 + lane;
            const int k2 = j2 - row - 1;
            const bool val2 = (lane < 16) && (k2 >= 0) && (k2 < KF) && (s0 + j2 < S);
            const float v2 = val2 ? s2 : NEG_BIG;

            float m = fmaxf(v1, v2);
            #pragma unroll
            for (int o = 16; o > 0; o >>= 1)
                m = fmaxf(m, __shfl_xor_sync(0xFFFFFFFFu, m, o));

            const float e1 = __expf(v1 - m);
            const float e2 = (lane < 16) ? __expf(v2 - m) : 0.0f;
            float sum = e1 + e2;
            #pragma unroll
            for (int o = 16; o > 0; o >>= 1)
                sum += __shfl_xor_sync(0xFFFFFFFFu, sum, o);
            const float inv = 1.0f / sum;

            const int wbase = WROW(row);
            const float w1 = val1 ? e1 * inv : 0.0f;
            Wd2[wbase + j1] = make_float2(w1, w1);
            if (lane < 16) {
                const float w2 = val2 ? e2 * inv : 0.0f;
                Wd2[wbase + j2] = make_float2(w2, w2);
            }
        }
        __syncthreads();   // weights ready

        // ===== Phase B: warp = 16 cols x 2 row-halves =====
        {
            const int w    = tid >> 5;      // 0..15
            const int lane = tid & 31;
            const int cl   = lane & 15;     // col within warp group
            const int h    = lane >> 4;     // row half 0/1
            const int b    = w * 16 + cl;   // f4 column 0..255

            int wrow[8];
            #pragma unroll
            for (int ii = 0; ii < 8; ++ii)
                wrow[ii] = WROW(h * 8 + ii);

            u64 acc[8][2];
            #pragma unroll
            for (int ii = 0; ii < 8; ++ii) { acc[ii][0] = 0ull; acc[ii][1] = 0ull; }

            // -- first 8 j-pairs: j 0..15 = the ring slots about to be recycled --
            #pragma unroll 2
            for (int jp = 0; jp < 8; ++jp) {
                const int jl = jp * 2;
                int sl1 = jl + rot;     if (sl1 >= ROWS) sl1 -= ROWS;
                int sl2 = jl + 1 + rot; if (sl2 >= ROWS) sl2 -= ROWS;
                const ulonglong2 f1 = tileU[sl1 * PITCH4 + b];
                const ulonglong2 f2 = tileU[sl2 * PITCH4 + b];
                #pragma unroll
                for (int ii = 0; ii < 8; ++ii) {
                    const ulonglong2 wp =
                        *reinterpret_cast<const ulonglong2*>(&Wd[wrow[ii] + jl]);
                    fma2(acc[ii][0], wp.x, f1.x);
                    fma2(acc[ii][1], wp.x, f1.y);
                    fma2(acc[ii][0], wp.y, f2.x);
                    fma2(acc[ii][1], wp.y, f2.y);
                }
            }

            __syncthreads();   // all warps done reading dying slots

            // -- async refresh into dead slots (no registers, latency hidden) --
            if (tt + 1 < CHAIN) {
                const int krow = tid >> 5;       // 0..15
                const int kcol = tid & 31;
                int slot = rot + krow; if (slot >= ROWS) slot -= ROWS;
                int gr = s0 + ROWS + krow;
                if (gr > S - 1) gr = S - 1;
                const float4* src = in4 + (size_t)gr * D4 + kcol;
                unsigned dst = (unsigned)__cvta_generic_to_shared(
                                   tile4 + slot * PITCH4 + kcol);
                #pragma unroll
                for (int c = 0; c < 8; ++c)
                    asm volatile("cp.async.cg.shared.global [%0], [%1], 16;\n"
                                 :: "r"(dst + c * 32 * 16), "l"(src + c * 32));
                asm volatile("cp.async.commit_group;\n");
            }

            // -- remaining 16 j-pairs: slots rot+16 .. rot+47 (disjoint) --
            #pragma unroll 2
            for (int jp = 8; jp < 24; ++jp) {
                const int jl = jp * 2;
                int sl1 = jl + rot;     if (sl1 >= ROWS) sl1 -= ROWS;
                int sl2 = jl + 1 + rot; if (sl2 >= ROWS) sl2 -= ROWS;
                const ulonglong2 f1 = tileU[sl1 * PITCH4 + b];
                const ulonglong2 f2 = tileU[sl2 * PITCH4 + b];
                #pragma unroll
                for (int ii = 0; ii < 8; ++ii) {
                    const ulonglong2 wp =
                        *reinterpret_cast<const ulonglong2*>(&Wd[wrow[ii] + jl]);
                    fma2(acc[ii][0], wp.x, f1.x);
                    fma2(acc[ii][1], wp.x, f1.y);
                    fma2(acc[ii][0], wp.y, f2.x);
                    fma2(acc[ii][1], wp.y, f2.y);
                }
            }

            #pragma unroll
            for (int ii = 0; ii < 8; ++ii) {
                const int s = s0 + h * 8 + ii;
                if (s < S) {
                    const float2 lo = *reinterpret_cast<float2*>(&acc[ii][0]);
                    const float2 hi = *reinterpret_cast<float2*>(&acc[ii][1]);
                    out4[(size_t)s * D4 + b] = make_float4(lo.x, lo.y, hi.x, hi.y);
                }
            }
        }

        // ---- drain refresh before next tile's phase A ----
        if (tt + 1 < CHAIN) {
            asm volatile("cp.async.wait_group 0;\n");
            rot += S_TILE; if (rot >= ROWS) rot -= ROWS;
        }
    }
}

extern "C" void kernel_launch(void* const* d_in, const int* in_sizes, int n_in,
                              void* d_out, int out_size)
{
    (void)n_in; (void)out_size;
    const float* in = (const float*)d_in[0];
    float* out = (float*)d_out;

    const int S = 2048;
    const int B = in_sizes[0] / (S * DCONST);
    const int chains = S / (S_TILE * CHAIN);   // 32

    cudaFuncSetAttribute(future_encoder_kernel,
                         cudaFuncAttributeMaxDynamicSharedMemorySize,
                         SMEM_BYTES);

    dim3 grid(chains, B);
    future_encoder_kernel<<<grid, 512, SMEM_BYTES>>>(in, out, S);
}

// round 14
// speedup vs baseline: 1.0465x; 1.0465x over previous
#include <cuda_runtime.h>

#define S_TILE   16
#define KF       32
#define ROWS     48            // S_TILE + KF (ring buffer size)
#define CHAIN    4             // s-tiles per CTA
#define DCONST   1024
#define D4       256           // D / 4
#define PITCH4   257           // float4 pitch per row
#define COLS     48
#define RPITCH   49            // red row pitch (floats) -> conflict-free partial stores
#define WPITCH   50            // weight-row pitch in u64 (even -> 16B aligned)
#define NEG_BIG  -1.0e9f

// weight row r at WROW(r) u64; +2 stagger per 8 rows keeps h0/h1 pairs bank-clean
#define WROW(r)  ((r) * WPITCH + (((r) >> 3) << 1))
#define W_U64    800

#define TILE_F4      (ROWS * PITCH4)              // 12336 f4
#define RED_OFF      (TILE_F4 * 4)                // 49344 floats
#define RED_SIZE     (8 * S_TILE * RPITCH)        // 6272 floats
#define W_OFF        (RED_OFF + RED_SIZE)         // 55616 (byte 222464: 16B aligned)
#define SMEM_FLOATS  (W_OFF + W_U64 * 2)
#define SMEM_BYTES   (SMEM_FLOATS * 4)            // 228864 B

typedef unsigned long long u64;

__device__ __forceinline__ void fma2(u64& d, u64 a, u64 b) {
    asm("fma.rn.f32x2 %0, %1, %2, %0;" : "+l"(d) : "l"(a), "l"(b));
}
__device__ __forceinline__ float sum2(u64 a) {
    float2 v = *reinterpret_cast<float2*>(&a);
    return v.x + v.y;
}

__global__ __launch_bounds__(512, 1)
void future_encoder_kernel(const float* __restrict__ in,
                           float* __restrict__ out,
                           int S)
{
    extern __shared__ float smem[];
    ulonglong2* tileU = reinterpret_cast<ulonglong2*>(smem);
    float4*     tile4 = reinterpret_cast<float4*>(smem);
    float*      red   = smem + RED_OFF;
    u64*        Wd    = reinterpret_cast<u64*>(smem + W_OFF);
    float2*     Wd2   = reinterpret_cast<float2*>(smem + W_OFF);

    const int tid   = threadIdx.x;
    const int chain = blockIdx.x;
    const int bb    = blockIdx.y;
    const int t0    = chain * CHAIN;

    const float4* in4  = reinterpret_cast<const float4*>(in)  + (size_t)bb * S * D4;
    float4*       out4 = reinterpret_cast<float4*>(out)       + (size_t)bb * S * D4;

    // ---- initial load: 48 rows into slots 0..47 ----
    {
        const int half = tid >> 8;
        const int col  = tid & 255;
        #pragma unroll 4
        for (int it = 0; it < 24; ++it) {
            const int r = it * 2 + half;
            int gr = t0 * S_TILE + r;
            if (gr > S - 1) gr = S - 1;
            tile4[r * PITCH4 + col] = in4[(size_t)gr * D4 + col];
        }
    }

    int rot = 0;

    for (int tt = 0; tt < CHAIN; ++tt) {
        const int s0 = (t0 + tt) * S_TILE;
        __syncthreads();   // ring consistent (incl. completed cp.async refresh)

        // ===== Phase A: warp = (d-group g, j-half); f software-pipelined =====
        {
            const int w    = tid >> 5;
            const int lane = tid & 31;
            const int g    = w >> 1;          // d-group 0..7 (128 dims)
            const int j0   = (w & 1) * 24;    // j half
            const int a    = lane >> 3;       // q rows a, a+4, a+8, a+12
            const int b    = lane & 7;        // f cols j0+b, +8, +16

            int qs[4], fs[3];
            #pragma unroll
            for (int ii = 0; ii < 4; ++ii) {
                int r = a + 4 * ii + rot; if (r >= ROWS) r -= ROWS;
                qs[ii] = r * PITCH4;
            }
            #pragma unroll
            for (int jj = 0; jj < 3; ++jj) {
                int r = j0 + b + 8 * jj + rot; if (r >= ROWS) r -= ROWS;
                fs[jj] = r * PITCH4;
            }

            u64 acc[4][3];
            #pragma unroll
            for (int ii = 0; ii < 4; ++ii)
                #pragma unroll
                for (int jj = 0; jj < 3; ++jj)
                    acc[ii][jj] = 0ull;

            const int base = g * 32;

            // preload f for step 0
            ulonglong2 f[3];
            #pragma unroll
            for (int jj = 0; jj < 3; ++jj)
                f[jj] = tileU[fs[jj] + base];

            #pragma unroll 4
            for (int step = 0; step < 32; ++step) {
                const int col = base + step;
                ulonglong2 q[4];
                #pragma unroll
                for (int ii = 0; ii < 4; ++ii)
                    q[ii] = tileU[qs[ii] + col];
                // prefetch f for step+1 (col+1 <= 256 < PITCH4: always in-bounds)
                ulonglong2 nf[3];
                #pragma unroll
                for (int jj = 0; jj < 3; ++jj)
                    nf[jj] = tileU[fs[jj] + col + 1];
                #pragma unroll
                for (int ii = 0; ii < 4; ++ii)
                    #pragma unroll
                    for (int jj = 0; jj < 3; ++jj) {
                        fma2(acc[ii][jj], q[ii].x, f[jj].x);
                        fma2(acc[ii][jj], q[ii].y, f[jj].y);
                    }
                #pragma unroll
                for (int jj = 0; jj < 3; ++jj)
                    f[jj] = nf[jj];
            }

            float* myred = red + g * (S_TILE * RPITCH);
            #pragma unroll
            for (int ii = 0; ii < 4; ++ii)
                #pragma unroll
                for (int jj = 0; jj < 3; ++jj)
                    myred[(a + 4 * ii) * RPITCH + (j0 + b + 8 * jj)] = sum2(acc[ii][jj]);
        }
        __syncthreads();   // red complete

        // ---- reduce over d-groups + mask + softmax (warp = query row) ----
        {
            const int row  = tid >> 5;
            const int lane = tid & 31;

            float s1 = 0.0f, s2 = 0.0f;
            #pragma unroll
            for (int g = 0; g < 8; ++g)
                s1 += red[g * (S_TILE * RPITCH) + row * RPITCH + lane];
            if (lane < 16) {
                #pragma unroll
                for (int g = 0; g < 8; ++g)
                    s2 += red[g * (S_TILE * RPITCH) + row * RPITCH + 32 + lane];
            }

            const int j1 = lane;
            const int k1 = j1 - row - 1;
            const bool val1 = (k1 >= 0) && (k1 < KF) && (s0 + j1 < S);
            const float v1 = val1 ? s1 : NEG_BIG;

            const int j2 = 32 + lane;
            const int k2 = j2 - row - 1;
            const bool val2 = (lane < 16) && (k2 >= 0) && (k2 < KF) && (s0 + j2 < S);
            const float v2 = val2 ? s2 : NEG_BIG;

            float m = fmaxf(v1, v2);
            #pragma unroll
            for (int o = 16; o > 0; o >>= 1)
                m = fmaxf(m, __shfl_xor_sync(0xFFFFFFFFu, m, o));

            const float e1 = __expf(v1 - m);
            const float e2 = (lane < 16) ? __expf(v2 - m) : 0.0f;
            float sum = e1 + e2;
            #pragma unroll
            for (int o = 16; o > 0; o >>= 1)
                sum += __shfl_xor_sync(0xFFFFFFFFu, sum, o);
            const float inv = 1.0f / sum;

            const int wbase = WROW(row);
            const float w1 = val1 ? e1 * inv : 0.0f;
            Wd2[wbase + j1] = make_float2(w1, w1);
            if (lane < 16) {
                const float w2 = val2 ? e2 * inv : 0.0f;
                Wd2[wbase + j2] = make_float2(w2, w2);
            }
        }
        __syncthreads();   // weights ready

        // ===== Phase B: warp = 16 cols x 2 row-halves; f software-pipelined =====
        {
            const int w    = tid >> 5;      // 0..15
            const int lane = tid & 31;
            const int cl   = lane & 15;     // col within warp group
            const int h    = lane >> 4;     // row half 0/1
            const int b    = w * 16 + cl;   // f4 column 0..255

            int wrow[8];
            #pragma unroll
            for (int ii = 0; ii < 8; ++ii)
                wrow[ii] = WROW(h * 8 + ii);

            u64 acc[8][2];
            #pragma unroll
            for (int ii = 0; ii < 8; ++ii) { acc[ii][0] = 0ull; acc[ii][1] = 0ull; }

            // slot index helper
            int sl1 = rot, sl2 = rot + 1; if (sl2 >= ROWS) sl2 -= ROWS;
            ulonglong2 f1 = tileU[sl1 * PITCH4 + b];
            ulonglong2 f2 = tileU[sl2 * PITCH4 + b];

            // -- first 8 j-pairs: j 0..15 = the ring slots about to be recycled --
            #pragma unroll
            for (int jp = 0; jp < 8; ++jp) {
                const int jl = jp * 2;
                // prefetch next pair (jp=7 preloads jp=8's slots: NOT recycled, safe)
                int nl1 = jl + 2 + rot; if (nl1 >= ROWS) nl1 -= ROWS;
                int nl2 = jl + 3 + rot; if (nl2 >= ROWS) nl2 -= ROWS;
                const ulonglong2 nf1 = tileU[nl1 * PITCH4 + b];
                const ulonglong2 nf2 = tileU[nl2 * PITCH4 + b];
                #pragma unroll
                for (int ii = 0; ii < 8; ++ii) {
                    const ulonglong2 wp =
                        *reinterpret_cast<const ulonglong2*>(&Wd[wrow[ii] + jl]);
                    fma2(acc[ii][0], wp.x, f1.x);
                    fma2(acc[ii][1], wp.x, f1.y);
                    fma2(acc[ii][0], wp.y, f2.x);
                    fma2(acc[ii][1], wp.y, f2.y);
                }
                f1 = nf1; f2 = nf2;
            }

            __syncthreads();   // all warps done reading dying slots

            // -- async refresh into dead slots (no registers, latency hidden) --
            if (tt + 1 < CHAIN) {
                const int krow = tid >> 5;       // 0..15
                const int kcol = tid & 31;
                int slot = rot + krow; if (slot >= ROWS) slot -= ROWS;
                int gr = s0 + ROWS + krow;
                if (gr > S - 1) gr = S - 1;
                const float4* src = in4 + (size_t)gr * D4 + kcol;
                unsigned dst = (unsigned)__cvta_generic_to_shared(
                                   tile4 + slot * PITCH4 + kcol);
                #pragma unroll
                for (int c = 0; c < 8; ++c)
                    asm volatile("cp.async.cg.shared.global [%0], [%1], 16;\n"
                                 :: "r"(dst + c * 32 * 16), "l"(src + c * 32));
                asm volatile("cp.async.commit_group;\n");
            }

            // -- remaining 16 j-pairs: slots rot+16 .. rot+47 (disjoint from refresh) --
            #pragma unroll 4
            for (int jp = 8; jp < 24; ++jp) {
                const int jl = jp * 2;
                // prefetch next pair (jp=23: clamp to reload current -> harmless)
                const int np = (jp < 23) ? jp + 1 : jp;
                int nl1 = np * 2 + rot;     if (nl1 >= ROWS) nl1 -= ROWS;
                int nl2 = np * 2 + 1 + rot; if (nl2 >= ROWS) nl2 -= ROWS;
                const ulonglong2 nf1 = tileU[nl1 * PITCH4 + b];
                const ulonglong2 nf2 = tileU[nl2 * PITCH4 + b];
                #pragma unroll
                for (int ii = 0; ii < 8; ++ii) {
                    const ulonglong2 wp =
                        *reinterpret_cast<const ulonglong2*>(&Wd[wrow[ii] + jl]);
                    fma2(acc[ii][0], wp.x, f1.x);
                    fma2(acc[ii][1], wp.x, f1.y);
                    fma2(acc[ii][0], wp.y, f2.x);
                    fma2(acc[ii][1], wp.y, f2.y);
                }
                f1 = nf1; f2 = nf2;
            }

            #pragma unroll
            for (int ii = 0; ii < 8; ++ii) {
                const int s = s0 + h * 8 + ii;
                if (s < S) {
                    const float2 lo = *reinterpret_cast<float2*>(&acc[ii][0]);
                    const float2 hi = *reinterpret_cast<float2*>(&acc[ii][1]);
                    out4[(size_t)s * D4 + b] = make_float4(lo.x, lo.y, hi.x, hi.y);
                }
            }
        }

        // ---- drain refresh before next tile's phase A ----
        if (tt + 1 < CHAIN) {
            asm volatile("cp.async.wait_group 0;\n");
            rot += S_TILE; if (rot >= ROWS) rot -= ROWS;
        }
    }
}

extern "C" void kernel_launch(void* const* d_in, const int* in_sizes, int n_in,
                              void* d_out, int out_size)
{
    (void)n_in; (void)out_size;
    const float* in = (const float*)d_in[0];
    float* out = (float*)d_out;

    const int S = 2048;
    const int B = in_sizes[0] / (S * DCONST);
    const int chains = S / (S_TILE * CHAIN);   // 32

    cudaFuncSetAttribute(future_encoder_kernel,
                         cudaFuncAttributeMaxDynamicSharedMemorySize,
                         SMEM_BYTES);

    dim3 grid(chains, B);
    future_encoder_kernel<<<grid, 512, SMEM_BYTES>>>(in, out, S);
}